// round 4
// baseline (speedup 1.0000x reference)
#include <cuda_runtime.h>
#include <cuda_fp16.h>
#include <cstddef>

#define NB 2
#define NC 128
#define NE 60000
#define TR_BLOCKS (2 * NB * 2 * (NE / 32))          // tensors*batch*chalf*etiles = 15000
#define W_WARPS   (2 * NC * 15 + 3)
#define W_BLOCKS  ((W_WARPS + 7) / 8)
#define GROUPS    (NB * NE / 4)

// packed f32x2 helpers (Blackwell FFMA2 path)
#define FMA_F32X2(d, a, b, c) \
    asm("fma.rn.f32x2 %0, %1, %2, %3;" : "=l"(d) : "l"(a), "l"(b), "l"(c))
#define PACKF(out, lo, hi) \
    asm("mov.b64 %0, {%1, %2};" : "=l"(out) : "f"(lo), "f"(hi))
#define UNPACKF(lo, hi, in) \
    asm("mov.b64 {%0, %1}, %2;" : "=f"(lo), "=f"(hi) : "l"(in))

// Transposed inputs in fp16: [tensor][b*E+e][c] (256B per edge row)
__device__ __half g_xth[2][(size_t)NB * NE * NC];
// Effective fused weights: [branch][c][s*3+k] padded to 16
__device__ float g_V[2][NC][16];
__device__ float g_cb[3];

// ---------------------------------------------------------------------------
// Kernel 1 (fused): blocks < TR_BLOCKS transpose x->fp16 (64c x 32e tiles);
// the remaining blocks fold the weights.
// ---------------------------------------------------------------------------
__global__ void __launch_bounds__(256)
prep_kernel(const float* __restrict__ x0, const float* __restrict__ x1,
    const float* __restrict__ Wa_local, const float* __restrict__ ba_local,
    const float* __restrict__ Wb_local, const float* __restrict__ bb_local,
    const float* __restrict__ Wa_tri,   const float* __restrict__ ba_tri,
    const float* __restrict__ Wb_tri,   const float* __restrict__ bb_tri,
    const float* __restrict__ Wa_fuse,  const float* __restrict__ ba_fuse,
    const float* __restrict__ Wb_fuse,  const float* __restrict__ bb_fuse)
{
    if (blockIdx.x < TR_BLOCKS) {
        __shared__ __half tile[32][66];   // [e_local][c_local], stride 66 halves
        int bx = blockIdx.x;
        const int eb = bx % (NE / 32);  bx /= (NE / 32);
        const int ch = bx & 1;          bx >>= 1;
        const int b  = bx & 1;
        const int tensor = bx >> 1;
        const float* __restrict__ src = tensor ? x1 : x0;
        const int e0 = eb * 32, c0 = ch * 64;
        const int tx = threadIdx.x & 31;
        const int ty = threadIdx.x >> 5;

#pragma unroll
        for (int i = 0; i < 8; i++) {
            int cl = ty + 8 * i;
            tile[tx][cl] = __float2half_rn(
                src[((size_t)b * NC + c0 + cl) * NE + e0 + tx]);
        }
        __syncthreads();
        __half* __restrict__ dst = g_xth[tensor];
#pragma unroll
        for (int it = 0; it < 4; it++) {
            int e = ty * 4 + it;
            unsigned v = *reinterpret_cast<const unsigned*>(&tile[e][2 * tx]);
            *reinterpret_cast<unsigned*>(
                dst + ((size_t)(b * NE + e0 + e)) * NC + c0 + 2 * tx) = v;
        }
        return;
    }

    // ---- weight folding: one warp per output ----
    const int lane = threadIdx.x & 31;
    const int w = (blockIdx.x - TR_BLOCKS) * 8 + (threadIdx.x >> 5);

    if (w < 2 * NC * 15) {
        const int t   = w / (NC * 15);
        const int rem = w - t * (NC * 15);
        const int c   = rem / 15;
        const int sk  = rem - c * 15;
        const int s   = sk / 3;
        const int k   = sk - s * 3;
        const float* Wf = t ? Wb_fuse  : Wa_fuse;
        const float* Wt = t ? Wb_tri   : Wa_tri;
        const float* Wl = t ? Wb_local : Wa_local;
        float acc = 0.f;
#pragma unroll
        for (int j = 0; j < 4; j++) {
            int o = lane + 32 * j;
            acc = fmaf(Wf[k * (2 * NC) + NC + o], Wt[(o * NC + c) * 5 + s], acc);
            if (s == 0)
                acc = fmaf(Wf[k * (2 * NC) + o], Wl[o * NC + c], acc);
        }
#pragma unroll
        for (int off = 16; off; off >>= 1)
            acc += __shfl_xor_sync(0xffffffffu, acc, off);
        if (lane == 0) {
            g_V[t][c][sk] = acc;
            if (sk == 0) g_V[t][c][15] = 0.f;
        }
    } else if (w < 2 * NC * 15 + 3) {
        const int k = w - 2 * NC * 15;
        float acc = 0.f;
#pragma unroll
        for (int j = 0; j < 4; j++) {
            int o = lane + 32 * j;
            acc = fmaf(Wa_fuse[k * 2 * NC + o],      ba_local[o], acc);
            acc = fmaf(Wa_fuse[k * 2 * NC + NC + o], ba_tri[o],   acc);
            acc = fmaf(Wb_fuse[k * 2 * NC + o],      bb_local[o], acc);
            acc = fmaf(Wb_fuse[k * 2 * NC + NC + o], bb_tri[o],   acc);
        }
#pragma unroll
        for (int off = 16; off; off >>= 1)
            acc += __shfl_xor_sync(0xffffffffu, acc, off);
        if (lane == 0)
            g_cb[k] = acc + ba_fuse[k] + bb_fuse[k];
    }
}

// ---------------------------------------------------------------------------
// Kernel 2: main gather + fused dot, packed f32x2 FMAs.
// 8 warps = 4 warp-pairs; warp w: tensor t=w>>2, pair p=w&3. Lane owns 4
// channels = 2 f32x2 pairs; 30 packed weights in registers.
// ---------------------------------------------------------------------------
__device__ __forceinline__ void ld2h2(const __half* __restrict__ p,
                                      __half2& a, __half2& b)
{
    uint2 u = *reinterpret_cast<const uint2*>(p);
    a = *reinterpret_cast<const __half2*>(&u.x);
    b = *reinterpret_cast<const __half2*>(&u.y);
}

__global__ void __launch_bounds__(256, 2)
mesh_main_kernel(const int* __restrict__ gemm, float* __restrict__ out)
{
    __shared__ float partial[2][2][4][12];   // [buf][t][pair][u*3+k]

    const int lane = threadIdx.x & 31;
    const int wid  = threadIdx.x >> 5;
    const int t    = wid >> 2;
    const int p    = wid & 3;
    const int pairIdx = blockIdx.x * 4 + p;
    const int P       = gridDim.x * 4;
    const int nIter   = (GROUPS + P - 1) / P;

    // own-tensor weights, packed per channel-pair: 30 x 64-bit = 60 regs
    unsigned long long Vp[2][15];
#pragma unroll
    for (int j2 = 0; j2 < 2; j2++) {
        const float* r0 = g_V[t][4 * lane + 2 * j2];
        const float* r1 = g_V[t][4 * lane + 2 * j2 + 1];
#pragma unroll
        for (int sk = 0; sk < 15; sk++)
            PACKF(Vp[j2][sk], r0[sk], r1[sk]);
    }
    float cbk = (lane < 12) ? g_cb[lane % 3] : 0.f;

    const int4* __restrict__ gi4 = reinterpret_cast<const int4*>(gemm);
    const __half* __restrict__ xt = g_xth[t];

    int buf = 0;
    for (int it = 0; it < nIter; it++, buf ^= 1) {
        const int g = pairIdx + it * P;
        const bool active = (g < GROUPS);
        int b = 0, ebase = 0;

        if (active) {
            const int e0 = 4 * g;
            b     = (e0 >= NE) ? 1 : 0;
            ebase = e0 - b * NE;
            const __half* __restrict__ base =
                xt + (size_t)b * NE * NC + lane * 4;

            float res[12];
#pragma unroll
            for (int u = 0; u < 4; u++) {
                const int e = ebase + u;
                const int4 gi = gi4[(size_t)b * NE + e];

                __half2 xs0, xs1, n10, n11, n20, n21, n30, n31, n40, n41;
                ld2h2(base + (size_t)e    * NC, xs0, xs1);
                ld2h2(base + (size_t)gi.x * NC, n10, n11);
                ld2h2(base + (size_t)gi.y * NC, n20, n21);
                ld2h2(base + (size_t)gi.z * NC, n30, n31);
                ld2h2(base + (size_t)gi.w * NC, n40, n41);

                __half2 f1a = __hadd2(n10, n30), f1b = __hadd2(n11, n31);
                __half2 f2a = __hadd2(n20, n40), f2b = __hadd2(n21, n41);
                __half2 f3a = __habs2(__hsub2(n10, n30));
                __half2 f3b = __habs2(__hsub2(n11, n31));
                __half2 f4a = __habs2(__hsub2(n20, n40));
                __half2 f4b = __habs2(__hsub2(n21, n41));

                unsigned long long Ga[5], Gb[5];
                {
                    float2 c0 = __half22float2(xs0); PACKF(Ga[0], c0.x, c0.y);
                    float2 c1 = __half22float2(f1a); PACKF(Ga[1], c1.x, c1.y);
                    float2 c2 = __half22float2(f2a); PACKF(Ga[2], c2.x, c2.y);
                    float2 c3 = __half22float2(f3a); PACKF(Ga[3], c3.x, c3.y);
                    float2 c4 = __half22float2(f4a); PACKF(Ga[4], c4.x, c4.y);
                    float2 d0 = __half22float2(xs1); PACKF(Gb[0], d0.x, d0.y);
                    float2 d1 = __half22float2(f1b); PACKF(Gb[1], d1.x, d1.y);
                    float2 d2 = __half22float2(f2b); PACKF(Gb[2], d2.x, d2.y);
                    float2 d3 = __half22float2(f3b); PACKF(Gb[3], d3.x, d3.y);
                    float2 d4 = __half22float2(f4b); PACKF(Gb[4], d4.x, d4.y);
                }

                unsigned long long a0 = 0ull, a1 = 0ull, a2 = 0ull;
#pragma unroll
                for (int s = 0; s < 5; s++) {
                    FMA_F32X2(a0, Vp[0][s * 3 + 0], Ga[s], a0);
                    FMA_F32X2(a1, Vp[0][s * 3 + 1], Ga[s], a1);
                    FMA_F32X2(a2, Vp[0][s * 3 + 2], Ga[s], a2);
                    FMA_F32X2(a0, Vp[1][s * 3 + 0], Gb[s], a0);
                    FMA_F32X2(a1, Vp[1][s * 3 + 1], Gb[s], a1);
                    FMA_F32X2(a2, Vp[1][s * 3 + 2], Gb[s], a2);
                }
                float lo, hi;
                UNPACKF(lo, hi, a0); res[u * 3 + 0] = lo + hi;
                UNPACKF(lo, hi, a1); res[u * 3 + 1] = lo + hi;
                UNPACKF(lo, hi, a2); res[u * 3 + 2] = lo + hi;
            }

#pragma unroll
            for (int off = 16; off; off >>= 1)
#pragma unroll
                for (int r = 0; r < 12; r++)
                    res[r] += __shfl_xor_sync(0xffffffffu, res[r], off);

            if (lane == 0) {
#pragma unroll
                for (int r = 0; r < 12; r++)
                    partial[buf][t][p][r] = res[r];
            }
        }
        __syncthreads();

        if (active && t == 0 && lane < 12) {
            const int u = lane / 3, k = lane - 3 * u;
            float v = partial[buf][0][p][lane] + partial[buf][1][p][lane] + cbk;
            out[((size_t)b * 3 + k) * NE + ebase + u] = v;
        }
    }
}

// ---------------------------------------------------------------------------
extern "C" void kernel_launch(void* const* d_in, const int* in_sizes, int n_in,
                              void* d_out, int out_size)
{
    const float* x_0      = (const float*)d_in[0];
    const float* x_1      = (const float*)d_in[1];
    const int*   gemm     = (const int*)  d_in[2];
    const float* Wa_local = (const float*)d_in[3];
    const float* ba_local = (const float*)d_in[4];
    const float* Wb_local = (const float*)d_in[5];
    const float* bb_local = (const float*)d_in[6];
    const float* Wa_tri   = (const float*)d_in[7];
    const float* ba_tri   = (const float*)d_in[8];
    const float* Wb_tri   = (const float*)d_in[9];
    const float* bb_tri   = (const float*)d_in[10];
    const float* Wa_fuse  = (const float*)d_in[11];
    const float* ba_fuse  = (const float*)d_in[12];
    const float* Wb_fuse  = (const float*)d_in[13];
    const float* bb_fuse  = (const float*)d_in[14];
    float* out = (float*)d_out;

    prep_kernel<<<TR_BLOCKS + W_BLOCKS, 256>>>(
        x_0, x_1,
        Wa_local, ba_local, Wb_local, bb_local,
        Wa_tri, ba_tri, Wb_tri, bb_tri,
        Wa_fuse, ba_fuse, Wb_fuse, bb_fuse);

    mesh_main_kernel<<<296, 256>>>(gemm, out);
}

// round 5
// speedup vs baseline: 1.1583x; 1.1583x over previous
#include <cuda_runtime.h>
#include <cuda_fp16.h>
#include <cstddef>

#define NB 2
#define NC 128
#define NE 60000
#define TR_BLOCKS (2 * NB * 2 * (NE / 32))          // 15000 transpose tiles
#define W_WARPS   (2 * NC * 15 + 3)
#define W_BLOCKS  ((W_WARPS + 7) / 8)
#define GROUPS    (NB * NE / 4)

// Transposed inputs in fp16: [tensor][b*E+e][c] (256B per edge row)
__device__ __half g_xth[2][(size_t)NB * NE * NC];
// Effective fused weights: [branch][c][s*3+k] padded to 16
__device__ float g_V[2][NC][16];
__device__ float g_cb[3];

// ---------------------------------------------------------------------------
// Kernel 1 (fused): blocks < TR_BLOCKS transpose x->fp16 (64c x 32e tiles);
// the remaining blocks fold the weights.
// ---------------------------------------------------------------------------
__global__ void __launch_bounds__(256)
prep_kernel(const float* __restrict__ x0, const float* __restrict__ x1,
    const float* __restrict__ Wa_local, const float* __restrict__ ba_local,
    const float* __restrict__ Wb_local, const float* __restrict__ bb_local,
    const float* __restrict__ Wa_tri,   const float* __restrict__ ba_tri,
    const float* __restrict__ Wb_tri,   const float* __restrict__ bb_tri,
    const float* __restrict__ Wa_fuse,  const float* __restrict__ ba_fuse,
    const float* __restrict__ Wb_fuse,  const float* __restrict__ bb_fuse)
{
    if (blockIdx.x < TR_BLOCKS) {
        __shared__ __half tile[32][66];   // [e_local][c_local], stride 66 halves
        int bx = blockIdx.x;
        const int eb = bx % (NE / 32);  bx /= (NE / 32);
        const int ch = bx & 1;          bx >>= 1;
        const int b  = bx & 1;
        const int tensor = bx >> 1;
        const float* __restrict__ src = tensor ? x1 : x0;
        const int e0 = eb * 32, c0 = ch * 64;
        const int tx = threadIdx.x & 31;
        const int ty = threadIdx.x >> 5;

#pragma unroll
        for (int i = 0; i < 8; i++) {
            int cl = ty + 8 * i;
            tile[tx][cl] = __float2half_rn(
                src[((size_t)b * NC + c0 + cl) * NE + e0 + tx]);
        }
        __syncthreads();
        __half* __restrict__ dst = g_xth[tensor];
#pragma unroll
        for (int it = 0; it < 4; it++) {
            int e = ty * 4 + it;
            unsigned v = *reinterpret_cast<const unsigned*>(&tile[e][2 * tx]);
            *reinterpret_cast<unsigned*>(
                dst + ((size_t)(b * NE + e0 + e)) * NC + c0 + 2 * tx) = v;
        }
        return;
    }

    // ---- weight folding: one warp per output ----
    const int lane = threadIdx.x & 31;
    const int w = (blockIdx.x - TR_BLOCKS) * 8 + (threadIdx.x >> 5);

    if (w < 2 * NC * 15) {
        const int t   = w / (NC * 15);
        const int rem = w - t * (NC * 15);
        const int c   = rem / 15;
        const int sk  = rem - c * 15;
        const int s   = sk / 3;
        const int k   = sk - s * 3;
        const float* Wf = t ? Wb_fuse  : Wa_fuse;
        const float* Wt = t ? Wb_tri   : Wa_tri;
        const float* Wl = t ? Wb_local : Wa_local;
        float acc = 0.f;
#pragma unroll
        for (int j = 0; j < 4; j++) {
            int o = lane + 32 * j;
            acc = fmaf(Wf[k * (2 * NC) + NC + o], Wt[(o * NC + c) * 5 + s], acc);
            if (s == 0)
                acc = fmaf(Wf[k * (2 * NC) + o], Wl[o * NC + c], acc);
        }
#pragma unroll
        for (int off = 16; off; off >>= 1)
            acc += __shfl_xor_sync(0xffffffffu, acc, off);
        if (lane == 0) {
            g_V[t][c][sk] = acc;
            if (sk == 0) g_V[t][c][15] = 0.f;
        }
    } else if (w < 2 * NC * 15 + 3) {
        const int k = w - 2 * NC * 15;
        float acc = 0.f;
#pragma unroll
        for (int j = 0; j < 4; j++) {
            int o = lane + 32 * j;
            acc = fmaf(Wa_fuse[k * 2 * NC + o],      ba_local[o], acc);
            acc = fmaf(Wa_fuse[k * 2 * NC + NC + o], ba_tri[o],   acc);
            acc = fmaf(Wb_fuse[k * 2 * NC + o],      bb_local[o], acc);
            acc = fmaf(Wb_fuse[k * 2 * NC + NC + o], bb_tri[o],   acc);
        }
#pragma unroll
        for (int off = 16; off; off >>= 1)
            acc += __shfl_xor_sync(0xffffffffu, acc, off);
        if (lane == 0)
            g_cb[k] = acc + ba_fuse[k] + bb_fuse[k];
    }
}

// ---------------------------------------------------------------------------
// Kernel 2: main gather + fused dot (scalar FFMA, load-batched 2 edges deep).
// 8 warps = 4 warp-pairs; warp w: tensor t=w>>2, pair p=w&3. Lane owns 4
// channels; 60 effective weights in registers.
// ---------------------------------------------------------------------------
__device__ __forceinline__ uint2 ldrow(const __half* __restrict__ p)
{
    return *reinterpret_cast<const uint2*>(p);
}

// compute one edge's 3 partials from 5 gathered rows, accumulate into a[3]
__device__ __forceinline__ void edge_fma(const uint2 r0, const uint2 r1,
                                         const uint2 r2, const uint2 r3,
                                         const uint2 r4,
                                         const float Vv[4][16], float* res)
{
    __half2 xs0 = *reinterpret_cast<const __half2*>(&r0.x);
    __half2 xs1 = *reinterpret_cast<const __half2*>(&r0.y);
    __half2 n1a = *reinterpret_cast<const __half2*>(&r1.x);
    __half2 n1b = *reinterpret_cast<const __half2*>(&r1.y);
    __half2 n2a = *reinterpret_cast<const __half2*>(&r2.x);
    __half2 n2b = *reinterpret_cast<const __half2*>(&r2.y);
    __half2 n3a = *reinterpret_cast<const __half2*>(&r3.x);
    __half2 n3b = *reinterpret_cast<const __half2*>(&r3.y);
    __half2 n4a = *reinterpret_cast<const __half2*>(&r4.x);
    __half2 n4b = *reinterpret_cast<const __half2*>(&r4.y);

    float2 G0a = __half22float2(xs0);
    float2 G0b = __half22float2(xs1);
    float2 G1a = __half22float2(__hadd2(n1a, n3a));
    float2 G1b = __half22float2(__hadd2(n1b, n3b));
    float2 G2a = __half22float2(__hadd2(n2a, n4a));
    float2 G2b = __half22float2(__hadd2(n2b, n4b));
    float2 G3a = __half22float2(__habs2(__hsub2(n1a, n3a)));
    float2 G3b = __half22float2(__habs2(__hsub2(n1b, n3b)));
    float2 G4a = __half22float2(__habs2(__hsub2(n2a, n4a)));
    float2 G4b = __half22float2(__habs2(__hsub2(n2b, n4b)));

    float a0 = 0.f, a1 = 0.f, a2 = 0.f;
#define ACC(s, GA, GB)                                             \
    a0 = fmaf(Vv[0][(s)*3+0], GA.x, a0);                           \
    a1 = fmaf(Vv[0][(s)*3+1], GA.x, a1);                           \
    a2 = fmaf(Vv[0][(s)*3+2], GA.x, a2);                           \
    a0 = fmaf(Vv[1][(s)*3+0], GA.y, a0);                           \
    a1 = fmaf(Vv[1][(s)*3+1], GA.y, a1);                           \
    a2 = fmaf(Vv[1][(s)*3+2], GA.y, a2);                           \
    a0 = fmaf(Vv[2][(s)*3+0], GB.x, a0);                           \
    a1 = fmaf(Vv[2][(s)*3+1], GB.x, a1);                           \
    a2 = fmaf(Vv[2][(s)*3+2], GB.x, a2);                           \
    a0 = fmaf(Vv[3][(s)*3+0], GB.y, a0);                           \
    a1 = fmaf(Vv[3][(s)*3+1], GB.y, a1);                           \
    a2 = fmaf(Vv[3][(s)*3+2], GB.y, a2);
    ACC(0, G0a, G0b)
    ACC(1, G1a, G1b)
    ACC(2, G2a, G2b)
    ACC(3, G3a, G3b)
    ACC(4, G4a, G4b)
#undef ACC
    res[0] = a0; res[1] = a1; res[2] = a2;
}

__global__ void __launch_bounds__(256, 2)
mesh_main_kernel(const int* __restrict__ gemm, float* __restrict__ out)
{
    __shared__ float partial[2][2][4][12];   // [buf][t][pair][u*3+k]

    const int lane = threadIdx.x & 31;
    const int wid  = threadIdx.x >> 5;
    const int t    = wid >> 2;
    const int p    = wid & 3;
    const int pairIdx = blockIdx.x * 4 + p;
    const int P       = gridDim.x * 4;
    const int nIter   = (GROUPS + P - 1) / P;

    // own-tensor weights: 60 live registers (pad col 15 unused)
    float Vv[4][16];
#pragma unroll
    for (int j = 0; j < 4; j++) {
        const float4* q = reinterpret_cast<const float4*>(g_V[t][4 * lane + j]);
        float4 q0 = q[0], q1 = q[1], q2 = q[2], q3 = q[3];
        Vv[j][0]  = q0.x; Vv[j][1]  = q0.y; Vv[j][2]  = q0.z; Vv[j][3]  = q0.w;
        Vv[j][4]  = q1.x; Vv[j][5]  = q1.y; Vv[j][6]  = q1.z; Vv[j][7]  = q1.w;
        Vv[j][8]  = q2.x; Vv[j][9]  = q2.y; Vv[j][10] = q2.z; Vv[j][11] = q2.w;
        Vv[j][12] = q3.x; Vv[j][13] = q3.y; Vv[j][14] = q3.z; Vv[j][15] = q3.w;
    }
    float cbk = (lane < 12) ? g_cb[lane % 3] : 0.f;

    const int4* __restrict__ gi4 = reinterpret_cast<const int4*>(gemm);
    const __half* __restrict__ xt = g_xth[t];

    int buf = 0;
    for (int it = 0; it < nIter; it++, buf ^= 1) {
        const int g = pairIdx + it * P;
        const bool active = (g < GROUPS);
        int b = 0, ebase = 0;

        if (active) {
            const int e0 = 4 * g;
            b     = (e0 >= NE) ? 1 : 0;
            ebase = e0 - b * NE;
            const __half* __restrict__ base =
                xt + (size_t)b * NE * NC + lane * 4;

            float res[12];
#pragma unroll
            for (int half = 0; half < 2; half++) {
                const int ea = ebase + 2 * half;
                // issue both gi loads, then all 10 row loads (MLP ~11)
                const int4 ga = gi4[(size_t)b * NE + ea];
                const int4 gb = gi4[(size_t)b * NE + ea + 1];

                uint2 ra0 = ldrow(base + (size_t)ea       * NC);
                uint2 ra1 = ldrow(base + (size_t)ga.x     * NC);
                uint2 ra2 = ldrow(base + (size_t)ga.y     * NC);
                uint2 ra3 = ldrow(base + (size_t)ga.z     * NC);
                uint2 ra4 = ldrow(base + (size_t)ga.w     * NC);
                uint2 rb0 = ldrow(base + (size_t)(ea + 1) * NC);
                uint2 rb1 = ldrow(base + (size_t)gb.x     * NC);
                uint2 rb2 = ldrow(base + (size_t)gb.y     * NC);
                uint2 rb3 = ldrow(base + (size_t)gb.z     * NC);
                uint2 rb4 = ldrow(base + (size_t)gb.w     * NC);

                edge_fma(ra0, ra1, ra2, ra3, ra4, Vv, res + 6 * half);
                edge_fma(rb0, rb1, rb2, rb3, rb4, Vv, res + 6 * half + 3);
            }

#pragma unroll
            for (int off = 16; off; off >>= 1)
#pragma unroll
                for (int r = 0; r < 12; r++)
                    res[r] += __shfl_xor_sync(0xffffffffu, res[r], off);

            if (lane == 0) {
#pragma unroll
                for (int r = 0; r < 12; r++)
                    partial[buf][t][p][r] = res[r];
            }
        }
        __syncthreads();

        if (active && t == 0 && lane < 12) {
            const int u = lane / 3, k = lane - 3 * u;
            float v = partial[buf][0][p][lane] + partial[buf][1][p][lane] + cbk;
            out[((size_t)b * 3 + k) * NE + ebase + u] = v;
        }
    }
}

// ---------------------------------------------------------------------------
extern "C" void kernel_launch(void* const* d_in, const int* in_sizes, int n_in,
                              void* d_out, int out_size)
{
    const float* x_0      = (const float*)d_in[0];
    const float* x_1      = (const float*)d_in[1];
    const int*   gemm     = (const int*)  d_in[2];
    const float* Wa_local = (const float*)d_in[3];
    const float* ba_local = (const float*)d_in[4];
    const float* Wb_local = (const float*)d_in[5];
    const float* bb_local = (const float*)d_in[6];
    const float* Wa_tri   = (const float*)d_in[7];
    const float* ba_tri   = (const float*)d_in[8];
    const float* Wb_tri   = (const float*)d_in[9];
    const float* bb_tri   = (const float*)d_in[10];
    const float* Wa_fuse  = (const float*)d_in[11];
    const float* ba_fuse  = (const float*)d_in[12];
    const float* Wb_fuse  = (const float*)d_in[13];
    const float* bb_fuse  = (const float*)d_in[14];
    float* out = (float*)d_out;

    prep_kernel<<<TR_BLOCKS + W_BLOCKS, 256>>>(
        x_0, x_1,
        Wa_local, ba_local, Wb_local, bb_local,
        Wa_tri, ba_tri, Wb_tri, bb_tri,
        Wa_fuse, ba_fuse, Wb_fuse, bb_fuse);

    mesh_main_kernel<<<296, 256>>>(gemm, out);
}